// round 7
// baseline (speedup 1.0000x reference)
#include <cuda_runtime.h>
#include <cuda_fp16.h>
#include <math.h>
#include <stdint.h>

// Problem constants
#define Nn   2048
#define CIN  2
#define Hh   32
#define EMB  16
#define HOR  12
#define Bb   32
#define Tt   16
#define KD   2048
#define GSTRIDE (Nn * 1024)

// Device scratch
__device__ __half g_Ah [Nn * Nn];       // adjacency fp16, [m][k] row-major
__device__ __half g_Rh [Nn * 1024];     // H fp16, [node(k)][b*32+h(n)]
__device__ __half g_Bxh[Nn * 1024];     // X all timesteps fp16
__device__ __half g_Gh [2 * GSTRIDE];   // split-K half-tiles (transfer buffer)
__device__ float  g_Gx [Nn * 1024];     // A @ X_all (summed, fp32)
__device__ float  g_C  [Nn * Bb * Hh];  // cell state, fragment-linear (private)
__device__ float  g_Hf [Nn * Bb * Hh];  // fp32 h [n][b][h], written at t=15
__device__ int    g_cnt[128];           // per-tile arrival counters (self-resetting)

// ---------------------------------------------------------------------------
__device__ __forceinline__ float fsig(float x) { return 1.0f / (1.0f + __expf(-x)); }
__device__ __forceinline__ float ftanh(float x) { return 2.0f / (1.0f + __expf(-2.0f * x)) - 1.0f; }

__device__ __forceinline__ void cp16(void* dst, const void* src) {
    uint32_t s = (uint32_t)__cvta_generic_to_shared(dst);
    asm volatile("cp.async.cg.shared.global [%0], [%1], 16;" :: "r"(s), "l"(src));
}

__device__ __forceinline__ void ldsm_x4(uint32_t (&r)[4], const void* p) {
    uint32_t a = (uint32_t)__cvta_generic_to_shared(p);
    asm volatile("ldmatrix.sync.aligned.m8n8.x4.shared.b16 {%0,%1,%2,%3}, [%4];"
                 : "=r"(r[0]), "=r"(r[1]), "=r"(r[2]), "=r"(r[3]) : "r"(a));
}
__device__ __forceinline__ void ldsm_x4_t(uint32_t (&r)[4], const void* p) {
    uint32_t a = (uint32_t)__cvta_generic_to_shared(p);
    asm volatile("ldmatrix.sync.aligned.m8n8.x4.trans.shared.b16 {%0,%1,%2,%3}, [%4];"
                 : "=r"(r[0]), "=r"(r[1]), "=r"(r[2]), "=r"(r[3]) : "r"(a));
}

__device__ __forceinline__ void mma_fp16(float (&d)[4], const uint32_t (&a)[4], const uint32_t* b) {
    asm volatile(
        "mma.sync.aligned.m16n8k16.row.col.f32.f16.f16.f32 "
        "{%0,%1,%2,%3}, {%4,%5,%6,%7}, {%8,%9}, {%0,%1,%2,%3};"
        : "+f"(d[0]), "+f"(d[1]), "+f"(d[2]), "+f"(d[3])
        : "r"(a[0]), "r"(a[1]), "r"(a[2]), "r"(a[3]), "r"(b[0]), "r"(b[1]));
}

// ---------------------------------------------------------------------------
// A = softmax(relu(E1 @ E2^T)) row-major [m][k], fp16
// ---------------------------------------------------------------------------
__global__ __launch_bounds__(256) void adj_kernel(const float* __restrict__ E1,
                                                  const float* __restrict__ E2) {
    int r = blockIdx.x;
    int tid = threadIdx.x;
    __shared__ float e1[EMB];
    __shared__ float red[256];
    if (tid < EMB) e1[tid] = E1[r * EMB + tid];
    __syncthreads();

    float v[8];
    float mx = -1e30f;
#pragma unroll
    for (int i = 0; i < 8; i++) {
        int c = tid + i * 256;
        float d = 0.f;
#pragma unroll
        for (int e = 0; e < EMB; e++) d += e1[e] * E2[c * EMB + e];
        d = fmaxf(d, 0.f);
        v[i] = d;
        mx = fmaxf(mx, d);
    }
    red[tid] = mx; __syncthreads();
    for (int s = 128; s > 0; s >>= 1) {
        if (tid < s) red[tid] = fmaxf(red[tid], red[tid + s]);
        __syncthreads();
    }
    mx = red[0]; __syncthreads();

    float sum = 0.f;
#pragma unroll
    for (int i = 0; i < 8; i++) { v[i] = expf(v[i] - mx); sum += v[i]; }
    red[tid] = sum; __syncthreads();
    for (int s = 128; s > 0; s >>= 1) {
        if (tid < s) red[tid] += red[tid + s];
        __syncthreads();
    }
    float inv = 1.0f / red[0];
#pragma unroll
    for (int i = 0; i < 8; i++)
        g_Ah[(size_t)r * Nn + tid + i * 256] = __float2half_rn(v[i] * inv);
}

// ---------------------------------------------------------------------------
__global__ __launch_bounds__(256) void buildx_kernel(const float* __restrict__ x) {
    int idx = blockIdx.x * 256 + threadIdx.x;
    int n = idx >> 10;
    int q = idx & 1023;
    int t = q >> 6;
    int r6 = q & 63;
    int b = r6 >> 1;
    int c = r6 & 1;
    g_Bxh[idx] = __float2half_rn(x[(((size_t)b * Tt + t) * Nn + n) * CIN + c]);
}

// g_Gx = (fp32) g_Gh[0..] + g_Gh[GSTRIDE..]
__global__ __launch_bounds__(256) void addx_kernel() {
    int i = blockIdx.x * 256 + threadIdx.x;
    __half2 a = ((const __half2*)g_Gh)[i];
    __half2 b = ((const __half2*)(g_Gh + GSTRIDE))[i];
    ((float2*)g_Gx)[i] = make_float2(__low2float(a) + __low2float(b),
                                     __high2float(a) + __high2float(b));
}

// ---------------------------------------------------------------------------
// Fused split-K fp16 GEMM + LSTM epilogue.
//   G_tile = A[:, z-half] @ B[z-half]; second-arriving CTA per (bx,by) does
//   the LSTM for its 128 nodes x 4 batches directly from registers + L2.
// t < 0: plain GEMM store only (for A @ X_all).
// ---------------------------------------------------------------------------
#define APITCH 40
#define BPITCH 136
#define ASZH (128 * APITCH)
#define BSZH (32 * BPITCH)
#define SSTAGEH (ASZH + BSZH)     // 9472 halves
#define SMEM_HALVES (3 * SSTAGEH) // 28416 halves = 56832 B
#define KSPLIT 1024
// epilogue smem layout (reusing the stage buffer):
#define GS_PITCH 40
#define EPI_WHS  20480            // Gs: 512*40 = 20480 halves
#define EPI_FLT  24832            // Whs: 32*136 = 4352 halves -> floats after

__global__ void __launch_bounds__(128, 2)
sgemm_fused(const __half* __restrict__ Ah, const __half* __restrict__ Bh,
            const float* __restrict__ Wx, const float* __restrict__ bx,
            const float* __restrict__ Wh, const float* __restrict__ bh,
            int t) {
    extern __shared__ __half smem[];
    __shared__ int s_old;
    int tid = threadIdx.x;
    int lane = tid & 31;
    int w = tid >> 5;
    int bm0 = blockIdx.y * 128;
    int bn0 = blockIdx.x * 128;
    int z = blockIdx.z;
    int kBase = z * KSPLIT;
    int wm0 = (w & 1) * 64;
    int wn0 = (w >> 1) * 64;

    float acc[4][8][4];
#pragma unroll
    for (int mt = 0; mt < 4; mt++)
#pragma unroll
        for (int nt = 0; nt < 8; nt++)
#pragma unroll
            for (int i = 0; i < 4; i++) acc[mt][nt][i] = 0.f;

    auto load_stage = [&](int s, int k0) {
        __half* sA = smem + s * SSTAGEH;
        __half* sB = sA + ASZH;
#pragma unroll
        for (int i = 0; i < 4; i++) {
            int ch = tid + i * 128;
            int r = ch >> 2;
            int c = ch & 3;
            cp16(sA + r * APITCH + c * 8,
                 Ah + (size_t)(bm0 + r) * KD + kBase + k0 + c * 8);
        }
#pragma unroll
        for (int i = 0; i < 4; i++) {
            int ch = tid + i * 128;
            int r = ch >> 4;
            int c = ch & 15;
            cp16(sB + r * BPITCH + c * 8,
                 Bh + (size_t)(kBase + k0 + r) * 1024 + bn0 + c * 8);
        }
    };

    load_stage(0, 0);
    asm volatile("cp.async.commit_group;" ::: "memory");
    load_stage(1, 32);
    asm volatile("cp.async.commit_group;" ::: "memory");

    const int NIT = KSPLIT / 32;
    for (int it = 0; it < NIT; ++it) {
        if (it + 2 < NIT) {
            asm volatile("cp.async.wait_group 1;" ::: "memory");
        } else {
            asm volatile("cp.async.wait_group 0;" ::: "memory");
        }
        __syncthreads();
        if (it + 2 < NIT) {
            load_stage((it + 2) % 3, (it + 2) * 32);
            asm volatile("cp.async.commit_group;" ::: "memory");
        }

        const __half* sA = smem + (it % 3) * SSTAGEH;
        const __half* sB = sA + ASZH;
#pragma unroll
        for (int kk = 0; kk < 2; kk++) {
            uint32_t a[4][4];
#pragma unroll
            for (int mt = 0; mt < 4; mt++) {
                ldsm_x4(a[mt], sA + (wm0 + mt * 16 + (lane & 15)) * APITCH
                               + kk * 16 + ((lane >> 4) << 3));
            }
            uint32_t b[8][2];
#pragma unroll
            for (int np = 0; np < 4; np++) {
                uint32_t t4[4];
                ldsm_x4_t(t4, sB + (kk * 16 + (lane & 15)) * BPITCH
                              + wn0 + np * 16 + ((lane >> 4) << 3));
                b[np * 2][0] = t4[0]; b[np * 2][1] = t4[1];
                b[np * 2 + 1][0] = t4[2]; b[np * 2 + 1][1] = t4[3];
            }
#pragma unroll
            for (int mt = 0; mt < 4; mt++)
#pragma unroll
                for (int nt = 0; nt < 8; nt++) mma_fp16(acc[mt][nt], a[mt], b[nt]);
        }
    }

    // store own half-tile to g_Gh[z]
    __half* Cown = g_Gh + (size_t)z * GSTRIDE;
#pragma unroll
    for (int mt = 0; mt < 4; mt++) {
        int r0 = bm0 + wm0 + mt * 16 + (lane >> 2);
#pragma unroll
        for (int nt = 0; nt < 8; nt++) {
            int c0 = bn0 + wn0 + nt * 8 + 2 * (lane & 3);
            *(__half2*)&Cown[(size_t)r0 * 1024 + c0] = __floats2half2_rn(acc[mt][nt][0], acc[mt][nt][1]);
            *(__half2*)&Cown[(size_t)(r0 + 8) * 1024 + c0] = __floats2half2_rn(acc[mt][nt][2], acc[mt][nt][3]);
        }
    }

    if (t < 0) return;   // plain GEMM mode (A @ X_all)

    // handshake: second arriver runs the LSTM for this tile
    int tile = blockIdx.y * 8 + blockIdx.x;
    __syncthreads();
    if (tid == 0) {
        __threadfence();
        s_old = atomicAdd(&g_cnt[tile], 1);
        if (s_old == 1) {
            g_cnt[tile] = 0;     // self-reset for next launch
            __threadfence();     // acquire: order partner-tile reads after atomic
        }
    }
    __syncthreads();
    if (s_old == 0) return;

    // ---------------- LSTM epilogue (second arriver) ----------------
    __half* Gs  = smem;                       // [512][GS_PITCH] fp16
    __half* Whs = smem + EPI_WHS;             // [32][BPITCH] fp16
    float*  fwx = (float*)(smem + EPI_FLT);   // Wx0[128], Wx1[128], bsum[128]
    float* Wx0 = fwx, *Wx1 = fwx + 128, *bsum = fwx + 256;

    // stage Gsum = own acc + partner half into Gs (lstm-row major: [node4+b][h])
    {
        const __half* Gpart = g_Gh + (size_t)(1 - z) * GSTRIDE;
#pragma unroll
        for (int mt = 0; mt < 4; mt++) {
            int rowC = wm0 + mt * 16 + (lane >> 2);     // node_local (+8 for hi)
#pragma unroll
            for (int nt = 0; nt < 8; nt++) {
                int col = wn0 + nt * 8 + 2 * (lane & 3);  // b_local*32 + h
                int bl = col >> 5, hh = col & 31;
                __half2 o0 = *(const __half2*)&Gpart[(size_t)(bm0 + rowC) * 1024 + bn0 + col];
                __half2 o1 = *(const __half2*)&Gpart[(size_t)(bm0 + rowC + 8) * 1024 + bn0 + col];
                float2 f0 = __half22float2(o0);
                float2 f1 = __half22float2(o1);
                *(__half2*)&Gs[(rowC * 4 + bl) * GS_PITCH + hh] =
                    __floats2half2_rn(acc[mt][nt][0] + f0.x, acc[mt][nt][1] + f0.y);
                *(__half2*)&Gs[((rowC + 8) * 4 + bl) * GS_PITCH + hh] =
                    __floats2half2_rn(acc[mt][nt][2] + f1.x, acc[mt][nt][3] + f1.y);
            }
        }
    }
    // load Wh / Wx / bias
    for (int i = tid; i < 4096; i += 128) {
        int k = i >> 7, g = i & 127;
        Whs[k * BPITCH + g] = __float2half_rn(Wh[i]);
    }
    if (tid < 128) {
        Wx0[tid] = Wx[tid];
        Wx1[tid] = Wx[128 + tid];
        bsum[tid] = bx[tid] + bh[tid];
    }
    __syncthreads();

    // Wh B-fragments (persist in regs): 16 n-frags x 2 k-frags
    uint32_t bf[2][16][2];
#pragma unroll
    for (int kk = 0; kk < 2; kk++) {
#pragma unroll
        for (int np = 0; np < 8; np++) {
            uint32_t t4[4];
            ldsm_x4_t(t4, Whs + (kk * 16 + (lane & 15)) * BPITCH
                          + np * 16 + ((lane >> 4) << 3));
            bf[kk][np * 2][0] = t4[0]; bf[kk][np * 2][1] = t4[1];
            bf[kk][np * 2 + 1][0] = t4[2]; bf[kk][np * 2 + 1][1] = t4[3];
        }
    }

    int b0g = bn0 >> 5;                 // first global batch of this tile
    int cole = 2 * (lane & 3);
    float2* Cp = (float2*)g_C;
    int tilewarp = tile * 4 + w;

#pragma unroll
    for (int mtile = 0; mtile < 8; mtile++) {
        int rowbase = w * 128 + mtile * 16;   // lstm-row base within tile (512 rows)
        uint32_t af[2][4];
#pragma unroll
        for (int kk = 0; kk < 2; kk++)
            ldsm_x4(af[kk], Gs + (rowbase + (lane & 15)) * GS_PITCH
                            + kk * 16 + ((lane >> 4) << 3));
        float ac2[16][4];
#pragma unroll
        for (int nt = 0; nt < 16; nt++) {
#pragma unroll
            for (int i = 0; i < 4; i++) ac2[nt][i] = 0.f;
            mma_fp16(ac2[nt], af[0], bf[0][nt]);
            mma_fp16(ac2[nt], af[1], bf[1][nt]);
        }

#pragma unroll
        for (int rs = 0; rs < 2; rs++) {
            int r = rowbase + rs * 8 + (lane >> 2);
            int node = bm0 + (r >> 2);
            int bg = b0g + (r & 3);
            float2 ax = *(const float2*)&g_Gx[(size_t)node * 1024 + t * 64 + bg * 2];
#pragma unroll
            for (int jj = 0; jj < 4; jj++) {
                int col = jj * 8 + cole;
                float gi0 = ac2[jj][rs * 2]      + ax.x * Wx0[col]      + ax.y * Wx1[col]      + bsum[col];
                float gi1 = ac2[jj][rs * 2 + 1]  + ax.x * Wx0[col + 1]  + ax.y * Wx1[col + 1]  + bsum[col + 1];
                float gf0 = ac2[jj + 4][rs * 2]     + ax.x * Wx0[32 + col]     + ax.y * Wx1[32 + col]     + bsum[32 + col];
                float gf1 = ac2[jj + 4][rs * 2 + 1] + ax.x * Wx0[32 + col + 1] + ax.y * Wx1[32 + col + 1] + bsum[32 + col + 1];
                float go0 = ac2[jj + 8][rs * 2]     + ax.x * Wx0[64 + col]     + ax.y * Wx1[64 + col]     + bsum[64 + col];
                float go1 = ac2[jj + 8][rs * 2 + 1] + ax.x * Wx0[64 + col + 1] + ax.y * Wx1[64 + col + 1] + bsum[64 + col + 1];
                float gg0 = ac2[jj + 12][rs * 2]     + ax.x * Wx0[96 + col]     + ax.y * Wx1[96 + col]     + bsum[96 + col];
                float gg1 = ac2[jj + 12][rs * 2 + 1] + ax.x * Wx0[96 + col + 1] + ax.y * Wx1[96 + col + 1] + bsum[96 + col + 1];

                float iv0 = fsig(gi0), iv1 = fsig(gi1);
                float fv0 = fsig(gf0), fv1 = fsig(gf1);
                float ov0 = fsig(go0), ov1 = fsig(go1);
                float gv0 = ftanh(gg0), gv1 = ftanh(gg1);

                int tslot = ((((tilewarp) * 8 + mtile) * 2 + rs) * 4 + jj) * 32 + lane;
                float2 cold = Cp[tslot];
                float cn0 = fv0 * cold.x + iv0 * gv0;
                float cn1 = fv1 * cold.y + iv1 * gv1;
                Cp[tslot] = make_float2(cn0, cn1);
                float h0 = ov0 * ftanh(cn0);
                float h1 = ov1 * ftanh(cn1);
                size_t haddr = (size_t)node * 1024 + bg * 32 + col;
                *(__half2*)&g_Rh[haddr] = __floats2half2_rn(h0, h1);
                if (t == Tt - 1) *(float2*)&g_Hf[haddr] = make_float2(h0, h1);
            }
        }
    }
}

// ---------------------------------------------------------------------------
// out[b, hz, n, 0] = sum_k h[b,n,k] * Wp[k,hz] + bp[hz]
// ---------------------------------------------------------------------------
__global__ __launch_bounds__(256) void proj_kernel(const float* __restrict__ Wp,
                                                   const float* __restrict__ bp,
                                                   float* __restrict__ out) {
    int idx = blockIdx.x * 256 + threadIdx.x;
    int n = idx & (Nn - 1);
    int b = idx >> 11;
    float hv[32];
#pragma unroll
    for (int k = 0; k < 32; k++) hv[k] = g_Hf[(size_t)n * 1024 + b * 32 + k];
#pragma unroll
    for (int hz = 0; hz < HOR; hz++) {
        float s = bp[hz];
#pragma unroll
        for (int k = 0; k < 32; k++) s += hv[k] * Wp[k * HOR + hz];
        out[((size_t)b * HOR + hz) * Nn + n] = s;
    }
}

// ---------------------------------------------------------------------------
extern "C" void kernel_launch(void* const* d_in, const int* in_sizes, int n_in,
                              void* d_out, int out_size) {
    const float* x  = (const float*)d_in[0];
    const float* E1 = (const float*)d_in[1];
    const float* E2 = (const float*)d_in[2];
    const float* Wx = (const float*)d_in[3];
    const float* bx = (const float*)d_in[4];
    const float* Wh = (const float*)d_in[5];
    const float* bh = (const float*)d_in[6];
    const float* Wp = (const float*)d_in[7];
    const float* bp = (const float*)d_in[8];
    float* out = (float*)d_out;

    void *pRh, *pC, *pAh, *pBxh, *pCnt;
    cudaGetSymbolAddress(&pRh, g_Rh);
    cudaGetSymbolAddress(&pC, g_C);
    cudaGetSymbolAddress(&pAh, g_Ah);
    cudaGetSymbolAddress(&pBxh, g_Bxh);
    cudaGetSymbolAddress(&pCnt, g_cnt);

    static int smem_set = 0;
    if (!smem_set) {
        cudaFuncSetAttribute(sgemm_fused, cudaFuncAttributeMaxDynamicSharedMemorySize,
                             SMEM_HALVES * (int)sizeof(__half));
        smem_set = 1;
    }

    cudaMemsetAsync(pRh, 0, sizeof(__half) * Nn * 1024, 0);
    cudaMemsetAsync(pC, 0, sizeof(float) * Nn * Bb * Hh, 0);
    cudaMemsetAsync(pCnt, 0, sizeof(int) * 128, 0);

    adj_kernel<<<Nn, 256>>>(E1, E2);
    buildx_kernel<<<(Nn * 1024) / 256, 256>>>(x);

    size_t gemmSmem = SMEM_HALVES * sizeof(__half);
    dim3 gemmGrid(1024 / 128, Nn / 128, 2);  // (8, 16, 2)

    // Gx = A @ X_all (plain GEMM mode)
    sgemm_fused<<<gemmGrid, 128, gemmSmem>>>((const __half*)pAh, (const __half*)pBxh,
                                             Wx, bx, Wh, bh, -1);
    addx_kernel<<<GSTRIDE / 512, 256>>>();

    for (int t = 0; t < Tt; t++) {
        sgemm_fused<<<gemmGrid, 128, gemmSmem>>>((const __half*)pAh, (const __half*)pRh,
                                                 Wx, bx, Wh, bh, t);
    }

    proj_kernel<<<(Bb * Nn) / 256, 256>>>(Wp, bp, out);
}

// round 8
// speedup vs baseline: 1.6842x; 1.6842x over previous
#include <cuda_runtime.h>
#include <cuda_fp16.h>
#include <math.h>
#include <stdint.h>

// Problem constants
#define Nn   2048
#define CIN  2
#define Hh   32
#define EMB  16
#define HOR  12
#define Bb   32
#define Tt   16
#define KD   2048
#define GSTRIDE (Nn * 1024)

// Device scratch
__device__ __half g_Ah [Nn * Nn];       // adjacency fp16, [m][k] row-major
__device__ __half g_Rh [Nn * 1024];     // H fp16, [node(k)][b*32+h(n)]
__device__ __half g_Bxh[Nn * 1024];     // X all timesteps fp16
__device__ __half g_Gh [2 * GSTRIDE];   // split-K halves of A @ H, fp16
__device__ float  g_Gx [Nn * 1024];     // A @ X_all (summed, fp32)
__device__ float  g_C  [Nn * Bb * Hh];  // cell state, fragment-linear (lstm-private)
__device__ float  g_Hf [Nn * Bb * Hh];  // fp32 h (normal layout), written at t=15

// ---------------------------------------------------------------------------
__device__ __forceinline__ float fsig(float x) { return 1.0f / (1.0f + __expf(-x)); }
__device__ __forceinline__ float ftanh(float x) { return 2.0f / (1.0f + __expf(-2.0f * x)) - 1.0f; }

__device__ __forceinline__ void cp16(void* dst, const void* src) {
    uint32_t s = (uint32_t)__cvta_generic_to_shared(dst);
    asm volatile("cp.async.cg.shared.global [%0], [%1], 16;" :: "r"(s), "l"(src));
}

__device__ __forceinline__ void ldsm_x4(uint32_t (&r)[4], const void* p) {
    uint32_t a = (uint32_t)__cvta_generic_to_shared(p);
    asm volatile("ldmatrix.sync.aligned.m8n8.x4.shared.b16 {%0,%1,%2,%3}, [%4];"
                 : "=r"(r[0]), "=r"(r[1]), "=r"(r[2]), "=r"(r[3]) : "r"(a));
}
__device__ __forceinline__ void ldsm_x4_t(uint32_t (&r)[4], const void* p) {
    uint32_t a = (uint32_t)__cvta_generic_to_shared(p);
    asm volatile("ldmatrix.sync.aligned.m8n8.x4.trans.shared.b16 {%0,%1,%2,%3}, [%4];"
                 : "=r"(r[0]), "=r"(r[1]), "=r"(r[2]), "=r"(r[3]) : "r"(a));
}

__device__ __forceinline__ void mma_fp16(float (&d)[4], const uint32_t (&a)[4], const uint32_t* b) {
    asm volatile(
        "mma.sync.aligned.m16n8k16.row.col.f32.f16.f16.f32 "
        "{%0,%1,%2,%3}, {%4,%5,%6,%7}, {%8,%9}, {%0,%1,%2,%3};"
        : "+f"(d[0]), "+f"(d[1]), "+f"(d[2]), "+f"(d[3])
        : "r"(a[0]), "r"(a[1]), "r"(a[2]), "r"(a[3]), "r"(b[0]), "r"(b[1]));
}

// ---------------------------------------------------------------------------
// A = softmax(relu(E1 @ E2^T)) row-major [m][k], fp16
// ---------------------------------------------------------------------------
__global__ __launch_bounds__(256) void adj_kernel(const float* __restrict__ E1,
                                                  const float* __restrict__ E2) {
    int r = blockIdx.x;
    int tid = threadIdx.x;
    __shared__ float e1[EMB];
    __shared__ float red[256];
    if (tid < EMB) e1[tid] = E1[r * EMB + tid];
    __syncthreads();

    float v[8];
    float mx = -1e30f;
#pragma unroll
    for (int i = 0; i < 8; i++) {
        int c = tid + i * 256;
        float d = 0.f;
#pragma unroll
        for (int e = 0; e < EMB; e++) d += e1[e] * E2[c * EMB + e];
        d = fmaxf(d, 0.f);
        v[i] = d;
        mx = fmaxf(mx, d);
    }
    red[tid] = mx; __syncthreads();
    for (int s = 128; s > 0; s >>= 1) {
        if (tid < s) red[tid] = fmaxf(red[tid], red[tid + s]);
        __syncthreads();
    }
    mx = red[0]; __syncthreads();

    float sum = 0.f;
#pragma unroll
    for (int i = 0; i < 8; i++) { v[i] = expf(v[i] - mx); sum += v[i]; }
    red[tid] = sum; __syncthreads();
    for (int s = 128; s > 0; s >>= 1) {
        if (tid < s) red[tid] += red[tid + s];
        __syncthreads();
    }
    float inv = 1.0f / red[0];
#pragma unroll
    for (int i = 0; i < 8; i++)
        g_Ah[(size_t)r * Nn + tid + i * 256] = __float2half_rn(v[i] * inv);
}

// ---------------------------------------------------------------------------
__global__ __launch_bounds__(256) void buildx_kernel(const float* __restrict__ x) {
    int idx = blockIdx.x * 256 + threadIdx.x;
    int n = idx >> 10;
    int q = idx & 1023;
    int t = q >> 6;
    int r6 = q & 63;
    int b = r6 >> 1;
    int c = r6 & 1;
    g_Bxh[idx] = __float2half_rn(x[(((size_t)b * Tt + t) * Nn + n) * CIN + c]);
}

// g_Gx = (fp32) g_Gh[0..] + g_Gh[GSTRIDE..]
__global__ __launch_bounds__(256) void addx_kernel() {
    int i = blockIdx.x * 256 + threadIdx.x;
    __half2 a = ((const __half2*)g_Gh)[i];
    __half2 b = ((const __half2*)(g_Gh + GSTRIDE))[i];
    ((float2*)g_Gx)[i] = make_float2(__low2float(a) + __low2float(b),
                                     __high2float(a) + __high2float(b));
}

// ---------------------------------------------------------------------------
// fp16 tensor-core GEMM, split-K (unchanged from R6 — known-good 26us/step)
// ---------------------------------------------------------------------------
#define APITCH 40
#define BPITCH 136
#define ASZH (128 * APITCH)
#define BSZH (32 * BPITCH)
#define SSTAGEH (ASZH + BSZH)
#define KSPLIT 1024

__global__ void __launch_bounds__(128, 2)
sgemm_fp16(const __half* __restrict__ Ah, const __half* __restrict__ Bh,
           __half* __restrict__ C) {
    extern __shared__ __half smem[];
    int tid = threadIdx.x;
    int lane = tid & 31;
    int w = tid >> 5;
    int bm0 = blockIdx.y * 128;
    int bn0 = blockIdx.x * 128;
    int kBase = blockIdx.z * KSPLIT;
    C += (size_t)blockIdx.z * GSTRIDE;
    int wm0 = (w & 1) * 64;
    int wn0 = (w >> 1) * 64;

    float acc[4][8][4];
#pragma unroll
    for (int mt = 0; mt < 4; mt++)
#pragma unroll
        for (int nt = 0; nt < 8; nt++)
#pragma unroll
            for (int i = 0; i < 4; i++) acc[mt][nt][i] = 0.f;

    auto load_stage = [&](int s, int k0) {
        __half* sA = smem + s * SSTAGEH;
        __half* sB = sA + ASZH;
#pragma unroll
        for (int i = 0; i < 4; i++) {
            int ch = tid + i * 128;
            int r = ch >> 2;
            int c = ch & 3;
            cp16(sA + r * APITCH + c * 8,
                 Ah + (size_t)(bm0 + r) * KD + kBase + k0 + c * 8);
        }
#pragma unroll
        for (int i = 0; i < 4; i++) {
            int ch = tid + i * 128;
            int r = ch >> 4;
            int c = ch & 15;
            cp16(sB + r * BPITCH + c * 8,
                 Bh + (size_t)(kBase + k0 + r) * 1024 + bn0 + c * 8);
        }
    };

    load_stage(0, 0);
    asm volatile("cp.async.commit_group;" ::: "memory");
    load_stage(1, 32);
    asm volatile("cp.async.commit_group;" ::: "memory");

    const int NIT = KSPLIT / 32;
    for (int it = 0; it < NIT; ++it) {
        if (it + 2 < NIT) {
            asm volatile("cp.async.wait_group 1;" ::: "memory");
        } else {
            asm volatile("cp.async.wait_group 0;" ::: "memory");
        }
        __syncthreads();
        if (it + 2 < NIT) {
            load_stage((it + 2) % 3, (it + 2) * 32);
            asm volatile("cp.async.commit_group;" ::: "memory");
        }

        const __half* sA = smem + (it % 3) * SSTAGEH;
        const __half* sB = sA + ASZH;
#pragma unroll
        for (int kk = 0; kk < 2; kk++) {
            uint32_t a[4][4];
#pragma unroll
            for (int mt = 0; mt < 4; mt++) {
                ldsm_x4(a[mt], sA + (wm0 + mt * 16 + (lane & 15)) * APITCH
                               + kk * 16 + ((lane >> 4) << 3));
            }
            uint32_t b[8][2];
#pragma unroll
            for (int np = 0; np < 4; np++) {
                uint32_t t4[4];
                ldsm_x4_t(t4, sB + (kk * 16 + (lane & 15)) * BPITCH
                              + wn0 + np * 16 + ((lane >> 4) << 3));
                b[np * 2][0] = t4[0]; b[np * 2][1] = t4[1];
                b[np * 2 + 1][0] = t4[2]; b[np * 2 + 1][1] = t4[3];
            }
#pragma unroll
            for (int mt = 0; mt < 4; mt++)
#pragma unroll
                for (int nt = 0; nt < 8; nt++) mma_fp16(acc[mt][nt], a[mt], b[nt]);
        }
    }

#pragma unroll
    for (int mt = 0; mt < 4; mt++) {
        int r0 = bm0 + wm0 + mt * 16 + (lane >> 2);
#pragma unroll
        for (int nt = 0; nt < 8; nt++) {
            int c0 = bn0 + wn0 + nt * 8 + 2 * (lane & 3);
            *(__half2*)&C[(size_t)r0 * 1024 + c0] = __floats2half2_rn(acc[mt][nt][0], acc[mt][nt][1]);
            *(__half2*)&C[(size_t)(r0 + 8) * 1024 + c0] = __floats2half2_rn(acc[mt][nt][2], acc[mt][nt][3]);
        }
    }
}

// ---------------------------------------------------------------------------
// LSTM with x-part/bias folded into the gate mma's K dimension (k=48):
//   Gext[row] = [Gsum(32) | ax0 ax1 1 0..], Whext = [Wh; Wx0; Wx1; bsum; 0..]
// Epilogue is pure pointwise math — no shared loads at all.
// ---------------------------------------------------------------------------
__global__ void __launch_bounds__(256, 2)
lstm_tc(const float* __restrict__ Wx, const float* __restrict__ bx,
        const float* __restrict__ Wh, const float* __restrict__ bh, int t) {
    __shared__ __half Whs[48 * BPITCH];
    int tid = threadIdx.x;
    // rows 0-31: Wh; 32: Wx0; 33: Wx1; 34: bx+bh; 35-47: 0
    for (int i = tid; i < 48 * 128; i += 256) {
        int k = i >> 7, g = i & 127;
        float v;
        if (k < 32)      v = Wh[k * 128 + g];
        else if (k == 32) v = Wx[g];
        else if (k == 33) v = Wx[128 + g];
        else if (k == 34) v = bx[g] + bh[g];
        else              v = 0.f;
        Whs[k * BPITCH + g] = __float2half_rn(v);
    }
    __syncthreads();

    int lane = tid & 31, warp = tid >> 5;
    int rowbase = blockIdx.x * 128 + warp * 16;
    int r_lo = rowbase + (lane >> 2);

    // x-part values for both fragment rows
    int n0 = r_lo >> 5, b0 = r_lo & 31;
    int r_hi = r_lo + 8;
    int n1 = r_hi >> 5, b1 = r_hi & 31;
    float2 axlo = *(const float2*)&g_Gx[(size_t)n0 * 1024 + t * 64 + b0 * 2];
    float2 axhi = *(const float2*)&g_Gx[(size_t)n1 * 1024 + t * 64 + b1 * 2];

    float acc[16][4];
#pragma unroll
    for (int nt = 0; nt < 16; nt++)
#pragma unroll
        for (int i = 0; i < 4; i++) acc[nt][i] = 0.f;

    const __half2* G0 = (const __half2*)g_Gh;
    const __half2* G1 = (const __half2*)(g_Gh + GSTRIDE);

#pragma unroll
    for (int kk = 0; kk < 3; kk++) {
        uint32_t a[4];
        if (kk < 2) {
            int idx = r_lo * 16 + kk * 8 + (lane & 3);   // half2 index
            int idxh = idx + 8 * 16;
            __half2 s0 = __hadd2(G0[idx],      G1[idx]);
            __half2 s1 = __hadd2(G0[idxh],     G1[idxh]);
            __half2 s2 = __hadd2(G0[idx + 4],  G1[idx + 4]);
            __half2 s3 = __hadd2(G0[idxh + 4], G1[idxh + 4]);
            a[0] = *reinterpret_cast<uint32_t*>(&s0);
            a[1] = *reinterpret_cast<uint32_t*>(&s1);
            a[2] = *reinterpret_cast<uint32_t*>(&s2);
            a[3] = *reinterpret_cast<uint32_t*>(&s3);
        } else {
            // k = 32 + (lane&3)*2 : sel 0 -> (ax0,ax1); sel 1 -> (1,0); else 0
            int sel = lane & 3;
            __half2 hlo = __floats2half2_rn(axlo.x, axlo.y);
            __half2 hhi = __floats2half2_rn(axhi.x, axhi.y);
            __half2 one = __floats2half2_rn(1.0f, 0.0f);
            uint32_t ulo = *reinterpret_cast<uint32_t*>(&hlo);
            uint32_t uhi = *reinterpret_cast<uint32_t*>(&hhi);
            uint32_t uon = *reinterpret_cast<uint32_t*>(&one);
            a[0] = (sel == 0) ? ulo : ((sel == 1) ? uon : 0u);
            a[1] = (sel == 0) ? uhi : ((sel == 1) ? uon : 0u);
            a[2] = 0u;
            a[3] = 0u;
        }
        uint32_t b[16][2];
#pragma unroll
        for (int np = 0; np < 8; np++) {
            uint32_t t4[4];
            ldsm_x4_t(t4, Whs + (kk * 16 + (lane & 15)) * BPITCH
                          + np * 16 + ((lane >> 4) << 3));
            b[np * 2][0] = t4[0]; b[np * 2][1] = t4[1];
            b[np * 2 + 1][0] = t4[2]; b[np * 2 + 1][1] = t4[3];
        }
#pragma unroll
        for (int nt = 0; nt < 16; nt++) mma_fp16(acc[nt], a, b[nt]);
    }

    int cole = 2 * (lane & 3);
    float2* Cp = (float2*)g_C;
#pragma unroll
    for (int rs = 0; rs < 2; rs++) {
        int r = r_lo + rs * 8;
        int n = r >> 5, b = r & 31;
#pragma unroll
        for (int j = 0; j < 4; j++) {
            int col = j * 8 + cole;
            float gi0 = acc[j][rs * 2],      gi1 = acc[j][rs * 2 + 1];
            float gf0 = acc[j + 4][rs * 2],  gf1 = acc[j + 4][rs * 2 + 1];
            float go0 = acc[j + 8][rs * 2],  go1 = acc[j + 8][rs * 2 + 1];
            float gg0 = acc[j + 12][rs * 2], gg1 = acc[j + 12][rs * 2 + 1];

            float iv0 = fsig(gi0), iv1 = fsig(gi1);
            float fv0 = fsig(gf0), fv1 = fsig(gf1);
            float ov0 = fsig(go0), ov1 = fsig(go1);
            float gv0 = ftanh(gg0), gv1 = ftanh(gg1);

            int tslot = ((((blockIdx.x * 8 + warp) * 2 + rs) * 4 + j) << 5) + lane;
            float2 cold = Cp[tslot];
            float cn0 = fv0 * cold.x + iv0 * gv0;
            float cn1 = fv1 * cold.y + iv1 * gv1;
            Cp[tslot] = make_float2(cn0, cn1);
            float h0 = ov0 * ftanh(cn0);
            float h1 = ov1 * ftanh(cn1);
            *(__half2*)&g_Rh[(size_t)n * 1024 + b * 32 + col] = __floats2half2_rn(h0, h1);
            if (t == Tt - 1) *(float2*)&g_Hf[(size_t)r * 32 + col] = make_float2(h0, h1);
        }
    }
}

// ---------------------------------------------------------------------------
__global__ __launch_bounds__(256) void proj_kernel(const float* __restrict__ Wp,
                                                   const float* __restrict__ bp,
                                                   float* __restrict__ out) {
    int idx = blockIdx.x * 256 + threadIdx.x;
    int n = idx & (Nn - 1);
    int b = idx >> 11;
    float hv[32];
#pragma unroll
    for (int k = 0; k < 32; k++) hv[k] = g_Hf[(size_t)n * 1024 + b * 32 + k];
#pragma unroll
    for (int hz = 0; hz < HOR; hz++) {
        float s = bp[hz];
#pragma unroll
        for (int k = 0; k < 32; k++) s += hv[k] * Wp[k * HOR + hz];
        out[((size_t)b * HOR + hz) * Nn + n] = s;
    }
}

// ---------------------------------------------------------------------------
extern "C" void kernel_launch(void* const* d_in, const int* in_sizes, int n_in,
                              void* d_out, int out_size) {
    const float* x  = (const float*)d_in[0];
    const float* E1 = (const float*)d_in[1];
    const float* E2 = (const float*)d_in[2];
    const float* Wx = (const float*)d_in[3];
    const float* bx = (const float*)d_in[4];
    const float* Wh = (const float*)d_in[5];
    const float* bh = (const float*)d_in[6];
    const float* Wp = (const float*)d_in[7];
    const float* bp = (const float*)d_in[8];
    float* out = (float*)d_out;

    void *pRh, *pC, *pAh, *pGh, *pBxh;
    cudaGetSymbolAddress(&pRh, g_Rh);
    cudaGetSymbolAddress(&pC, g_C);
    cudaGetSymbolAddress(&pAh, g_Ah);
    cudaGetSymbolAddress(&pGh, g_Gh);
    cudaGetSymbolAddress(&pBxh, g_Bxh);

    static int smem_set = 0;
    if (!smem_set) {
        cudaFuncSetAttribute(sgemm_fp16, cudaFuncAttributeMaxDynamicSharedMemorySize,
                             3 * SSTAGEH * (int)sizeof(__half));
        smem_set = 1;
    }

    cudaMemsetAsync(pRh, 0, sizeof(__half) * Nn * 1024, 0);
    cudaMemsetAsync(pC, 0, sizeof(float) * Nn * Bb * Hh, 0);

    adj_kernel<<<Nn, 256>>>(E1, E2);
    buildx_kernel<<<(Nn * 1024) / 256, 256>>>(x);

    size_t gemmSmem = 3 * SSTAGEH * sizeof(__half);
    dim3 gemmGrid(1024 / 128, Nn / 128, 2);  // (8, 16, 2)

    // Gx = A @ X_all
    sgemm_fp16<<<gemmGrid, 128, gemmSmem>>>((const __half*)pAh, (const __half*)pBxh,
                                            (__half*)pGh);
    addx_kernel<<<GSTRIDE / 512, 256>>>();

    for (int t = 0; t < Tt; t++) {
        sgemm_fp16<<<gemmGrid, 128, gemmSmem>>>((const __half*)pAh, (const __half*)pRh,
                                                (__half*)pGh);
        lstm_tc<<<(Nn * Bb) / 128, 256>>>(Wx, bx, Wh, bh, t);
    }

    proj_kernel<<<(Bb * Nn) / 256, 256>>>(Wp, bp, out);
}

// round 9
// speedup vs baseline: 1.6913x; 1.0042x over previous
#include <cuda_runtime.h>
#include <cuda_fp16.h>
#include <math.h>
#include <stdint.h>

// Problem constants
#define Nn   2048
#define CIN  2
#define Hh   32
#define EMB  16
#define HOR  12
#define Bb   32
#define Tt   16
#define KD   2048
#define GSTRIDE (Nn * 1024)

// Device scratch
__device__ __half g_Ah [Nn * Nn];       // adjacency fp16, [m][k] row-major
__device__ __half g_Rh [Nn * 1024];     // H fp16, [node(k)][b*32+h(n)]
__device__ __half g_Bxh[Nn * 1024];     // X all timesteps fp16
__device__ __half g_Gh [2 * GSTRIDE];   // split-K halves of A @ H, fp16
__device__ float  g_Gx [Nn * 1024];     // A @ X_all (summed, fp32)
__device__ float  g_C  [Nn * Bb * Hh];  // cell state, fragment-linear (lstm-private)
__device__ float  g_Hf [Nn * Bb * Hh];  // fp32 h (normal layout), written at t=15

// ---------------------------------------------------------------------------
__device__ __forceinline__ float fsig(float x) { return 1.0f / (1.0f + __expf(-x)); }
__device__ __forceinline__ float ftanh(float x) { return 2.0f / (1.0f + __expf(-2.0f * x)) - 1.0f; }

__device__ __forceinline__ void cp16(void* dst, const void* src) {
    uint32_t s = (uint32_t)__cvta_generic_to_shared(dst);
    asm volatile("cp.async.cg.shared.global [%0], [%1], 16;" :: "r"(s), "l"(src));
}

__device__ __forceinline__ void ldsm_x4(uint32_t (&r)[4], const void* p) {
    uint32_t a = (uint32_t)__cvta_generic_to_shared(p);
    asm volatile("ldmatrix.sync.aligned.m8n8.x4.shared.b16 {%0,%1,%2,%3}, [%4];"
                 : "=r"(r[0]), "=r"(r[1]), "=r"(r[2]), "=r"(r[3]) : "r"(a));
}
__device__ __forceinline__ void ldsm_x4_t(uint32_t (&r)[4], const void* p) {
    uint32_t a = (uint32_t)__cvta_generic_to_shared(p);
    asm volatile("ldmatrix.sync.aligned.m8n8.x4.trans.shared.b16 {%0,%1,%2,%3}, [%4];"
                 : "=r"(r[0]), "=r"(r[1]), "=r"(r[2]), "=r"(r[3]) : "r"(a));
}

__device__ __forceinline__ void mma_fp16(float (&d)[4], const uint32_t (&a)[4], const uint32_t* b) {
    asm volatile(
        "mma.sync.aligned.m16n8k16.row.col.f32.f16.f16.f32 "
        "{%0,%1,%2,%3}, {%4,%5,%6,%7}, {%8,%9}, {%0,%1,%2,%3};"
        : "+f"(d[0]), "+f"(d[1]), "+f"(d[2]), "+f"(d[3])
        : "r"(a[0]), "r"(a[1]), "r"(a[2]), "r"(a[3]), "r"(b[0]), "r"(b[1]));
}

// ---------------------------------------------------------------------------
// A = softmax(relu(E1 @ E2^T)) row-major [m][k], fp16
// ---------------------------------------------------------------------------
__global__ __launch_bounds__(256) void adj_kernel(const float* __restrict__ E1,
                                                  const float* __restrict__ E2) {
    int r = blockIdx.x;
    int tid = threadIdx.x;
    __shared__ float e1[EMB];
    __shared__ float red[256];
    if (tid < EMB) e1[tid] = E1[r * EMB + tid];
    __syncthreads();

    float v[8];
    float mx = -1e30f;
#pragma unroll
    for (int i = 0; i < 8; i++) {
        int c = tid + i * 256;
        float d = 0.f;
#pragma unroll
        for (int e = 0; e < EMB; e++) d += e1[e] * E2[c * EMB + e];
        d = fmaxf(d, 0.f);
        v[i] = d;
        mx = fmaxf(mx, d);
    }
    red[tid] = mx; __syncthreads();
    for (int s = 128; s > 0; s >>= 1) {
        if (tid < s) red[tid] = fmaxf(red[tid], red[tid + s]);
        __syncthreads();
    }
    mx = red[0]; __syncthreads();

    float sum = 0.f;
#pragma unroll
    for (int i = 0; i < 8; i++) { v[i] = expf(v[i] - mx); sum += v[i]; }
    red[tid] = sum; __syncthreads();
    for (int s = 128; s > 0; s >>= 1) {
        if (tid < s) red[tid] += red[tid + s];
        __syncthreads();
    }
    float inv = 1.0f / red[0];
#pragma unroll
    for (int i = 0; i < 8; i++)
        g_Ah[(size_t)r * Nn + tid + i * 256] = __float2half_rn(v[i] * inv);
}

// ---------------------------------------------------------------------------
__global__ __launch_bounds__(256) void buildx_kernel(const float* __restrict__ x) {
    int idx = blockIdx.x * 256 + threadIdx.x;
    int n = idx >> 10;
    int q = idx & 1023;
    int t = q >> 6;
    int r6 = q & 63;
    int b = r6 >> 1;
    int c = r6 & 1;
    g_Bxh[idx] = __float2half_rn(x[(((size_t)b * Tt + t) * Nn + n) * CIN + c]);
}

// g_Gx = (fp32) g_Gh[0..] + g_Gh[GSTRIDE..]
__global__ __launch_bounds__(256) void addx_kernel() {
    int i = blockIdx.x * 256 + threadIdx.x;
    __half2 a = ((const __half2*)g_Gh)[i];
    __half2 b = ((const __half2*)(g_Gh + GSTRIDE))[i];
    ((float2*)g_Gx)[i] = make_float2(__low2float(a) + __low2float(b),
                                     __high2float(a) + __high2float(b));
}

// ---------------------------------------------------------------------------
// fp16 tensor-core GEMM, split-K (unchanged — known-good 26us/step)
// ---------------------------------------------------------------------------
#define APITCH 40
#define BPITCH 136
#define ASZH (128 * APITCH)
#define BSZH (32 * BPITCH)
#define SSTAGEH (ASZH + BSZH)
#define KSPLIT 1024

__global__ void __launch_bounds__(128, 2)
sgemm_fp16(const __half* __restrict__ Ah, const __half* __restrict__ Bh,
           __half* __restrict__ C) {
    extern __shared__ __half smem[];
    int tid = threadIdx.x;
    int lane = tid & 31;
    int w = tid >> 5;
    int bm0 = blockIdx.y * 128;
    int bn0 = blockIdx.x * 128;
    int kBase = blockIdx.z * KSPLIT;
    C += (size_t)blockIdx.z * GSTRIDE;
    int wm0 = (w & 1) * 64;
    int wn0 = (w >> 1) * 64;

    float acc[4][8][4];
#pragma unroll
    for (int mt = 0; mt < 4; mt++)
#pragma unroll
        for (int nt = 0; nt < 8; nt++)
#pragma unroll
            for (int i = 0; i < 4; i++) acc[mt][nt][i] = 0.f;

    auto load_stage = [&](int s, int k0) {
        __half* sA = smem + s * SSTAGEH;
        __half* sB = sA + ASZH;
#pragma unroll
        for (int i = 0; i < 4; i++) {
            int ch = tid + i * 128;
            int r = ch >> 2;
            int c = ch & 3;
            cp16(sA + r * APITCH + c * 8,
                 Ah + (size_t)(bm0 + r) * KD + kBase + k0 + c * 8);
        }
#pragma unroll
        for (int i = 0; i < 4; i++) {
            int ch = tid + i * 128;
            int r = ch >> 4;
            int c = ch & 15;
            cp16(sB + r * BPITCH + c * 8,
                 Bh + (size_t)(kBase + k0 + r) * 1024 + bn0 + c * 8);
        }
    };

    load_stage(0, 0);
    asm volatile("cp.async.commit_group;" ::: "memory");
    load_stage(1, 32);
    asm volatile("cp.async.commit_group;" ::: "memory");

    const int NIT = KSPLIT / 32;
    for (int it = 0; it < NIT; ++it) {
        if (it + 2 < NIT) {
            asm volatile("cp.async.wait_group 1;" ::: "memory");
        } else {
            asm volatile("cp.async.wait_group 0;" ::: "memory");
        }
        __syncthreads();
        if (it + 2 < NIT) {
            load_stage((it + 2) % 3, (it + 2) * 32);
            asm volatile("cp.async.commit_group;" ::: "memory");
        }

        const __half* sA = smem + (it % 3) * SSTAGEH;
        const __half* sB = sA + ASZH;
#pragma unroll
        for (int kk = 0; kk < 2; kk++) {
            uint32_t a[4][4];
#pragma unroll
            for (int mt = 0; mt < 4; mt++) {
                ldsm_x4(a[mt], sA + (wm0 + mt * 16 + (lane & 15)) * APITCH
                               + kk * 16 + ((lane >> 4) << 3));
            }
            uint32_t b[8][2];
#pragma unroll
            for (int np = 0; np < 4; np++) {
                uint32_t t4[4];
                ldsm_x4_t(t4, sB + (kk * 16 + (lane & 15)) * BPITCH
                              + wn0 + np * 16 + ((lane >> 4) << 3));
                b[np * 2][0] = t4[0]; b[np * 2][1] = t4[1];
                b[np * 2 + 1][0] = t4[2]; b[np * 2 + 1][1] = t4[3];
            }
#pragma unroll
            for (int mt = 0; mt < 4; mt++)
#pragma unroll
                for (int nt = 0; nt < 8; nt++) mma_fp16(acc[mt][nt], a[mt], b[nt]);
        }
    }

#pragma unroll
    for (int mt = 0; mt < 4; mt++) {
        int r0 = bm0 + wm0 + mt * 16 + (lane >> 2);
#pragma unroll
        for (int nt = 0; nt < 8; nt++) {
            int c0 = bn0 + wn0 + nt * 8 + 2 * (lane & 3);
            *(__half2*)&C[(size_t)r0 * 1024 + c0] = __floats2half2_rn(acc[mt][nt][0], acc[mt][nt][1]);
            *(__half2*)&C[(size_t)(r0 + 8) * 1024 + c0] = __floats2half2_rn(acc[mt][nt][2], acc[mt][nt][3]);
        }
    }
}

// ---------------------------------------------------------------------------
// LSTM (k=48 folded gates) with smem-staged, coalesced G loads.
// G is lstm-row-major: g_Gh[r*32 + h], r = node*32+b. CTA handles 128 rows.
// ---------------------------------------------------------------------------
__global__ void __launch_bounds__(256, 2)
lstm_tc(const float* __restrict__ Wx, const float* __restrict__ bx,
        const float* __restrict__ Wh, const float* __restrict__ bh, int t) {
    __shared__ __half Whs[48 * BPITCH];     // 13056 B
    __shared__ __half Gs0[128 * APITCH];    // 10240 B
    __shared__ __half Gs1[128 * APITCH];    // 10240 B
    int tid = threadIdx.x;
    int rbase = blockIdx.x * 128;

    // stage both G halves, coalesced 16B per thread
#pragma unroll
    for (int i = 0; i < 2; i++) {
        int ch = tid + i * 256;
        int r = ch >> 2, c = ch & 3;
        cp16(Gs0 + r * APITCH + c * 8, g_Gh + (size_t)(rbase + r) * 32 + c * 8);
        cp16(Gs1 + r * APITCH + c * 8, g_Gh + GSTRIDE + (size_t)(rbase + r) * 32 + c * 8);
    }
    asm volatile("cp.async.commit_group;" ::: "memory");

    // rows 0-31: Wh; 32: Wx0; 33: Wx1; 34: bx+bh; 35-47: 0
    for (int i = tid; i < 48 * 128; i += 256) {
        int k = i >> 7, g = i & 127;
        float v;
        if (k < 32)       v = Wh[k * 128 + g];
        else if (k == 32) v = Wx[g];
        else if (k == 33) v = Wx[128 + g];
        else if (k == 34) v = bx[g] + bh[g];
        else              v = 0.f;
        Whs[k * BPITCH + g] = __float2half_rn(v);
    }
    asm volatile("cp.async.wait_group 0;" ::: "memory");
    __syncthreads();

    int lane = tid & 31, warp = tid >> 5;
    int wrow = warp * 16;               // warp's row block within CTA
    int r_lo = rbase + wrow + (lane >> 2);

    // x-part values for both fragment rows
    int n0 = r_lo >> 5, b0 = r_lo & 31;
    int r_hi = r_lo + 8;
    int n1 = r_hi >> 5, b1 = r_hi & 31;
    float2 axlo = *(const float2*)&g_Gx[(size_t)n0 * 1024 + t * 64 + b0 * 2];
    float2 axhi = *(const float2*)&g_Gx[(size_t)n1 * 1024 + t * 64 + b1 * 2];

    float acc[16][4];
#pragma unroll
    for (int nt = 0; nt < 16; nt++)
#pragma unroll
        for (int i = 0; i < 4; i++) acc[nt][i] = 0.f;

#pragma unroll
    for (int kk = 0; kk < 3; kk++) {
        uint32_t a[4];
        if (kk < 2) {
            uint32_t a0[4], a1[4];
            const __half* p0 = Gs0 + (wrow + (lane & 15)) * APITCH + kk * 16 + ((lane >> 4) << 3);
            const __half* p1 = Gs1 + (wrow + (lane & 15)) * APITCH + kk * 16 + ((lane >> 4) << 3);
            ldsm_x4(a0, p0);
            ldsm_x4(a1, p1);
#pragma unroll
            for (int i = 0; i < 4; i++) {
                __half2 s = __hadd2(*reinterpret_cast<__half2*>(&a0[i]),
                                    *reinterpret_cast<__half2*>(&a1[i]));
                a[i] = *reinterpret_cast<uint32_t*>(&s);
            }
        } else {
            // k = 32 + (lane&3)*2 : sel 0 -> (ax0,ax1); sel 1 -> (1,0); else 0
            int sel = lane & 3;
            __half2 hlo = __floats2half2_rn(axlo.x, axlo.y);
            __half2 hhi = __floats2half2_rn(axhi.x, axhi.y);
            __half2 one = __floats2half2_rn(1.0f, 0.0f);
            uint32_t ulo = *reinterpret_cast<uint32_t*>(&hlo);
            uint32_t uhi = *reinterpret_cast<uint32_t*>(&hhi);
            uint32_t uon = *reinterpret_cast<uint32_t*>(&one);
            a[0] = (sel == 0) ? ulo : ((sel == 1) ? uon : 0u);
            a[1] = (sel == 0) ? uhi : ((sel == 1) ? uon : 0u);
            a[2] = 0u;
            a[3] = 0u;
        }
        uint32_t b[16][2];
#pragma unroll
        for (int np = 0; np < 8; np++) {
            uint32_t t4[4];
            ldsm_x4_t(t4, Whs + (kk * 16 + (lane & 15)) * BPITCH
                          + np * 16 + ((lane >> 4) << 3));
            b[np * 2][0] = t4[0]; b[np * 2][1] = t4[1];
            b[np * 2 + 1][0] = t4[2]; b[np * 2 + 1][1] = t4[3];
        }
#pragma unroll
        for (int nt = 0; nt < 16; nt++) mma_fp16(acc[nt], a, b[nt]);
    }

    int cole = 2 * (lane & 3);
    float2* Cp = (float2*)g_C;
#pragma unroll
    for (int rs = 0; rs < 2; rs++) {
        int r = r_lo + rs * 8;
#pragma unroll
        for (int j = 0; j < 4; j++) {
            int col = j * 8 + cole;
            float gi0 = acc[j][rs * 2],      gi1 = acc[j][rs * 2 + 1];
            float gf0 = acc[j + 4][rs * 2],  gf1 = acc[j + 4][rs * 2 + 1];
            float go0 = acc[j + 8][rs * 2],  go1 = acc[j + 8][rs * 2 + 1];
            float gg0 = acc[j + 12][rs * 2], gg1 = acc[j + 12][rs * 2 + 1];

            float iv0 = fsig(gi0), iv1 = fsig(gi1);
            float fv0 = fsig(gf0), fv1 = fsig(gf1);
            float ov0 = fsig(go0), ov1 = fsig(go1);
            float gv0 = ftanh(gg0), gv1 = ftanh(gg1);

            int tslot = ((((blockIdx.x * 8 + warp) * 2 + rs) * 4 + j) << 5) + lane;
            float2 cold = Cp[tslot];
            float cn0 = fv0 * cold.x + iv0 * gv0;
            float cn1 = fv1 * cold.y + iv1 * gv1;
            Cp[tslot] = make_float2(cn0, cn1);
            float h0 = ov0 * ftanh(cn0);
            float h1 = ov1 * ftanh(cn1);
            *(__half2*)&g_Rh[(size_t)r * 32 + col] = __floats2half2_rn(h0, h1);
            if (t == Tt - 1) *(float2*)&g_Hf[(size_t)r * 32 + col] = make_float2(h0, h1);
        }
    }
}

// ---------------------------------------------------------------------------
__global__ __launch_bounds__(256) void proj_kernel(const float* __restrict__ Wp,
                                                   const float* __restrict__ bp,
                                                   float* __restrict__ out) {
    int idx = blockIdx.x * 256 + threadIdx.x;
    int n = idx & (Nn - 1);
    int b = idx >> 11;
    float hv[32];
#pragma unroll
    for (int k = 0; k < 32; k++) hv[k] = g_Hf[(size_t)n * 1024 + b * 32 + k];
#pragma unroll
    for (int hz = 0; hz < HOR; hz++) {
        float s = bp[hz];
#pragma unroll
        for (int k = 0; k < 32; k++) s += hv[k] * Wp[k * HOR + hz];
        out[((size_t)b * HOR + hz) * Nn + n] = s;
    }
}

// ---------------------------------------------------------------------------
extern "C" void kernel_launch(void* const* d_in, const int* in_sizes, int n_in,
                              void* d_out, int out_size) {
    const float* x  = (const float*)d_in[0];
    const float* E1 = (const float*)d_in[1];
    const float* E2 = (const float*)d_in[2];
    const float* Wx = (const float*)d_in[3];
    const float* bx = (const float*)d_in[4];
    const float* Wh = (const float*)d_in[5];
    const float* bh = (const float*)d_in[6];
    const float* Wp = (const float*)d_in[7];
    const float* bp = (const float*)d_in[8];
    float* out = (float*)d_out;

    void *pRh, *pC, *pAh, *pGh, *pBxh;
    cudaGetSymbolAddress(&pRh, g_Rh);
    cudaGetSymbolAddress(&pC, g_C);
    cudaGetSymbolAddress(&pAh, g_Ah);
    cudaGetSymbolAddress(&pGh, g_Gh);
    cudaGetSymbolAddress(&pBxh, g_Bxh);

    static int smem_set = 0;
    if (!smem_set) {
        cudaFuncSetAttribute(sgemm_fp16, cudaFuncAttributeMaxDynamicSharedMemorySize,
                             3 * SSTAGEH * (int)sizeof(__half));
        smem_set = 1;
    }

    cudaMemsetAsync(pRh, 0, sizeof(__half) * Nn * 1024, 0);
    cudaMemsetAsync(pC, 0, sizeof(float) * Nn * Bb * Hh, 0);

    adj_kernel<<<Nn, 256>>>(E1, E2);
    buildx_kernel<<<(Nn * 1024) / 256, 256>>>(x);

    size_t gemmSmem = 3 * SSTAGEH * sizeof(__half);
    dim3 gemmGrid(1024 / 128, Nn / 128, 2);  // (8, 16, 2)

    // Gx = A @ X_all
    sgemm_fp16<<<gemmGrid, 128, gemmSmem>>>((const __half*)pAh, (const __half*)pBxh,
                                            (__half*)pGh);
    addx_kernel<<<GSTRIDE / 512, 256>>>();

    for (int t = 0; t < Tt; t++) {
        sgemm_fp16<<<gemmGrid, 128, gemmSmem>>>((const __half*)pAh, (const __half*)pRh,
                                                (__half*)pGh);
        lstm_tc<<<(Nn * Bb) / 128, 256>>>(Wx, bx, Wh, bh, t);
    }

    proj_kernel<<<(Bb * Nn) / 256, 256>>>(Wp, bp, out);
}